// round 3
// baseline (speedup 1.0000x reference)
#include <cuda_runtime.h>
#include <cstdint>

#define N_NODES 100000
#define N_EDGES 1600000
#define D 128

// Static scratch (no allocations allowed)
__device__ float g_h[(size_t)N_NODES * D];     // h = x @ W
__device__ int   g_count[N_NODES];             // per-dst degree histogram
__device__ int   g_off[N_NODES + 1];           // CSR row offsets
__device__ int   g_cursor[N_NODES];            // fill cursors (copy of offsets)
__device__ int2  g_edge[N_EDGES];              // (edge_id, src) grouped by dst

// ---------------------------------------------------------------------------
// Kernel 1: zero the histogram (fresh every launch; graph replays reuse state)
// ---------------------------------------------------------------------------
__global__ void zero_counts_kernel() {
    int i = blockIdx.x * blockDim.x + threadIdx.x;
    if (i < N_NODES) g_count[i] = 0;
}

// ---------------------------------------------------------------------------
// Kernel 2: histogram of destination nodes
// ---------------------------------------------------------------------------
__global__ __launch_bounds__(256) void hist_kernel(const int* __restrict__ ei) {
    int e = blockIdx.x * blockDim.x + threadIdx.x;
    if (e < N_EDGES) atomicAdd(&g_count[__ldg(&ei[N_EDGES + e])], 1);
}

// ---------------------------------------------------------------------------
// Kernel 3: h = x @ W  (4 warps/block, 4 rows/warp, float4 per lane)
// ---------------------------------------------------------------------------
#define ROWS_PER_WARP 4
#define ROWS_PER_BLOCK (4 * ROWS_PER_WARP)  // 16; 100000/16 = 6250 exact

__global__ __launch_bounds__(128) void gemm_kernel(const float* __restrict__ x,
                                                   const float* __restrict__ W) {
    __shared__ float xs[ROWS_PER_BLOCK][D];
    int tid  = threadIdx.x;
    int warp = tid >> 5;
    int lane = tid & 31;
    int row0 = blockIdx.x * ROWS_PER_BLOCK;

    const float4* xsrc = (const float4*)(x + (size_t)row0 * D);
    float4* xdst = (float4*)&xs[0][0];
    #pragma unroll
    for (int i = 0; i < ROWS_PER_BLOCK * D / 4 / 128; i++)
        xdst[tid + i * 128] = xsrc[tid + i * 128];
    __syncthreads();

    const float4* W4 = (const float4*)W;  // [D][32] float4
    for (int r = 0; r < ROWS_PER_WARP; r++) {
        int lr = warp * ROWS_PER_WARP + r;
        float4 acc = make_float4(0.f, 0.f, 0.f, 0.f);
        #pragma unroll
        for (int k = 0; k < D; k++) {
            float xv = xs[lr][k];
            float4 w = __ldg(&W4[k * 32 + lane]);
            acc.x += xv * w.x;
            acc.y += xv * w.y;
            acc.z += xv * w.z;
            acc.w += xv * w.w;
        }
        ((float4*)(g_h + (size_t)(row0 + lr) * D))[lane] = acc;
    }
}

// ---------------------------------------------------------------------------
// Kernel 4: single-block exclusive scan of g_count -> g_off, g_cursor
// ---------------------------------------------------------------------------
__global__ __launch_bounds__(1024) void scan_kernel() {
    int tid = threadIdx.x, lane = tid & 31, wid = tid >> 5;
    __shared__ int wsum[32];
    __shared__ int s_carry;
    if (tid == 0) s_carry = 0;
    __syncthreads();

    for (int base = 0; base < N_NODES; base += 1024) {
        int idx = base + tid;
        int v = (idx < N_NODES) ? g_count[idx] : 0;
        // warp inclusive scan
        int inc = v;
        #pragma unroll
        for (int d = 1; d < 32; d <<= 1) {
            int t = __shfl_up_sync(0xFFFFFFFFu, inc, d);
            if (lane >= d) inc += t;
        }
        if (lane == 31) wsum[wid] = inc;
        __syncthreads();
        if (wid == 0) {
            int wv = wsum[lane];
            int winc = wv;
            #pragma unroll
            for (int d = 1; d < 32; d <<= 1) {
                int t = __shfl_up_sync(0xFFFFFFFFu, winc, d);
                if (lane >= d) winc += t;
            }
            wsum[lane] = winc - wv;  // exclusive warp offsets
        }
        __syncthreads();
        int excl = s_carry + wsum[wid] + inc - v;
        if (idx < N_NODES) { g_off[idx] = excl; g_cursor[idx] = excl; }
        __syncthreads();
        if (tid == 1023) s_carry = excl + v;  // old carry + chunk total
        __syncthreads();
    }
    if (tid == 0) g_off[N_NODES] = s_carry;  // == N_EDGES
}

// ---------------------------------------------------------------------------
// Kernel 5: fill permuted edge list grouped by dst
// ---------------------------------------------------------------------------
__global__ __launch_bounds__(256) void fill_kernel(const int* __restrict__ ei) {
    int e = blockIdx.x * blockDim.x + threadIdx.x;
    if (e >= N_EDGES) return;
    int src = __ldg(&ei[e]);
    int dst = __ldg(&ei[N_EDGES + e]);
    int pos = atomicAdd(&g_cursor[dst], 1);
    g_edge[pos] = make_int2(e, src);
}

// ---------------------------------------------------------------------------
// Kernel 6: gather-side aggregation. One warp per node, float4 per lane.
// out[n] = bias + sum_{e: dst==n} relu(h[src_e] + edge_attr[e])
// ---------------------------------------------------------------------------
__global__ __launch_bounds__(256) void gather_kernel(const float* __restrict__ ea,
                                                     const float* __restrict__ bias,
                                                     float* __restrict__ out) {
    int n = blockIdx.x * (blockDim.x >> 5) + (threadIdx.x >> 5);
    if (n >= N_NODES) return;
    int lane = threadIdx.x & 31;

    int beg = __ldg(&g_off[n]);
    int end = __ldg(&g_off[n + 1]);

    float4 acc = make_float4(0.f, 0.f, 0.f, 0.f);
    for (int base = beg; base < end; base += 32) {
        int m = min(32, end - base);
        int2 es = (base + lane < end) ? __ldg(&g_edge[base + lane]) : make_int2(0, 0);
        for (int j = 0; j < m; j++) {
            int e = __shfl_sync(0xFFFFFFFFu, es.x, j);
            int s = __shfl_sync(0xFFFFFFFFu, es.y, j);
            float4 a = __ldg(&((const float4*)(ea + (size_t)e * D))[lane]);
            float4 h = ((const float4*)(g_h + (size_t)s * D))[lane];
            acc.x += fmaxf(h.x + a.x, 0.f);
            acc.y += fmaxf(h.y + a.y, 0.f);
            acc.z += fmaxf(h.z + a.z, 0.f);
            acc.w += fmaxf(h.w + a.w, 0.f);
        }
    }
    float4 b = __ldg(&((const float4*)bias)[lane]);
    acc.x += b.x; acc.y += b.y; acc.z += b.z; acc.w += b.w;
    ((float4*)(out + (size_t)n * D))[lane] = acc;
}

// ---------------------------------------------------------------------------
extern "C" void kernel_launch(void* const* d_in, const int* in_sizes, int n_in,
                              void* d_out, int out_size) {
    const float* x    = (const float*)d_in[0];
    const int*   ei   = (const int*)d_in[1];   // int32 (JAX x64-disabled)
    const float* ea   = (const float*)d_in[2];
    const float* W    = (const float*)d_in[3];
    const float* bias = (const float*)d_in[4];
    float*       out  = (float*)d_out;

    zero_counts_kernel<<<(N_NODES + 255) / 256, 256>>>();
    hist_kernel<<<(N_EDGES + 255) / 256, 256>>>(ei);
    gemm_kernel<<<N_NODES / ROWS_PER_BLOCK, 128>>>(x, W);
    scan_kernel<<<1, 1024>>>();
    fill_kernel<<<(N_EDGES + 255) / 256, 256>>>(ei);
    gather_kernel<<<(N_NODES * 32 + 255) / 256, 256>>>(ea, bias, out);
}

// round 4
// speedup vs baseline: 1.2346x; 1.2346x over previous
#include <cuda_runtime.h>
#include <cstdint>

#define N_NODES 100000
#define N_EDGES 1600000
#define D 128
#define SCAN_NB 98  // ceil(100000 / 1024)

// Static scratch (no allocations allowed)
__device__ float g_h[(size_t)N_NODES * D];     // h = x @ W
__device__ int   g_count[N_NODES];             // per-dst degree histogram
__device__ int   g_off[N_NODES + 1];           // CSR row offsets
__device__ int   g_cursor[N_NODES];            // fill cursors
__device__ int   g_bsum[SCAN_NB];              // per-block scan sums
__device__ int2  g_edge[N_EDGES];              // (edge_id, src) grouped by dst

// ---------------------------------------------------------------------------
// Kernel 1: zero the histogram
// ---------------------------------------------------------------------------
__global__ void zero_counts_kernel() {
    int i = blockIdx.x * blockDim.x + threadIdx.x;
    if (i < N_NODES) g_count[i] = 0;
}

// ---------------------------------------------------------------------------
// Kernel 2: histogram of destination nodes (int4-vectorized reads)
// ---------------------------------------------------------------------------
__global__ __launch_bounds__(256) void hist_kernel(const int* __restrict__ ei) {
    int t = blockIdx.x * blockDim.x + threadIdx.x;  // one thread = 4 edges
    if (t * 4 >= N_EDGES) return;
    int4 d4 = __ldg(&((const int4*)(ei + N_EDGES))[t]);
    atomicAdd(&g_count[d4.x], 1);
    atomicAdd(&g_count[d4.y], 1);
    atomicAdd(&g_count[d4.z], 1);
    atomicAdd(&g_count[d4.w], 1);
}

// ---------------------------------------------------------------------------
// Kernel 3: h = x @ W  (4 warps/block, 4 rows/warp, float4 per lane)
// ---------------------------------------------------------------------------
#define ROWS_PER_WARP 4
#define ROWS_PER_BLOCK (4 * ROWS_PER_WARP)  // 16; 100000/16 = 6250 exact

__global__ __launch_bounds__(128) void gemm_kernel(const float* __restrict__ x,
                                                   const float* __restrict__ W) {
    __shared__ float xs[ROWS_PER_BLOCK][D];
    int tid  = threadIdx.x;
    int warp = tid >> 5;
    int lane = tid & 31;
    int row0 = blockIdx.x * ROWS_PER_BLOCK;

    const float4* xsrc = (const float4*)(x + (size_t)row0 * D);
    float4* xdst = (float4*)&xs[0][0];
    #pragma unroll
    for (int i = 0; i < ROWS_PER_BLOCK * D / 4 / 128; i++)
        xdst[tid + i * 128] = xsrc[tid + i * 128];
    __syncthreads();

    const float4* W4 = (const float4*)W;  // [D][32] float4
    for (int r = 0; r < ROWS_PER_WARP; r++) {
        int lr = warp * ROWS_PER_WARP + r;
        float4 acc = make_float4(0.f, 0.f, 0.f, 0.f);
        #pragma unroll
        for (int k = 0; k < D; k++) {
            float xv = xs[lr][k];
            float4 w = __ldg(&W4[k * 32 + lane]);
            acc.x += xv * w.x;
            acc.y += xv * w.y;
            acc.z += xv * w.z;
            acc.w += xv * w.w;
        }
        ((float4*)(g_h + (size_t)(row0 + lr) * D))[lane] = acc;
    }
}

// ---------------------------------------------------------------------------
// Kernel 4a: per-block local exclusive scan (98 blocks x 1024)
// ---------------------------------------------------------------------------
__global__ __launch_bounds__(1024) void scan_local_kernel() {
    __shared__ int wsum[32];
    int tid = threadIdx.x, lane = tid & 31, wid = tid >> 5;
    int idx = blockIdx.x * 1024 + tid;
    int v = (idx < N_NODES) ? g_count[idx] : 0;

    int inc = v;
    #pragma unroll
    for (int d = 1; d < 32; d <<= 1) {
        int t = __shfl_up_sync(0xFFFFFFFFu, inc, d);
        if (lane >= d) inc += t;
    }
    if (lane == 31) wsum[wid] = inc;
    __syncthreads();
    if (wid == 0) {
        int wv = wsum[lane];
        int winc = wv;
        #pragma unroll
        for (int d = 1; d < 32; d <<= 1) {
            int t = __shfl_up_sync(0xFFFFFFFFu, winc, d);
            if (lane >= d) winc += t;
        }
        wsum[lane] = winc - wv;
    }
    __syncthreads();
    int excl = wsum[wid] + inc - v;  // block-local exclusive
    if (idx < N_NODES) g_off[idx] = excl;
    if (tid == 1023) g_bsum[blockIdx.x] = excl + v;  // block total
}

// ---------------------------------------------------------------------------
// Kernel 4b: scan the 98 block sums (1 block, 128 threads)
// ---------------------------------------------------------------------------
__global__ __launch_bounds__(128) void scan_bsum_kernel() {
    __shared__ int wsum[4];
    int tid = threadIdx.x, lane = tid & 31, wid = tid >> 5;
    int v = (tid < SCAN_NB) ? g_bsum[tid] : 0;
    int inc = v;
    #pragma unroll
    for (int d = 1; d < 32; d <<= 1) {
        int t = __shfl_up_sync(0xFFFFFFFFu, inc, d);
        if (lane >= d) inc += t;
    }
    if (lane == 31) wsum[wid] = inc;
    __syncthreads();
    int woff = 0;
    for (int w = 0; w < wid; w++) woff += wsum[w];
    if (tid < SCAN_NB) g_bsum[tid] = woff + inc - v;  // exclusive
    if (tid == 127) g_off[N_NODES] = woff + inc;      // total == N_EDGES
}

// ---------------------------------------------------------------------------
// Kernel 4c: add block offsets -> final g_off, g_cursor
// ---------------------------------------------------------------------------
__global__ void scan_add_kernel() {
    int idx = blockIdx.x * blockDim.x + threadIdx.x;
    if (idx < N_NODES) {
        int o = g_off[idx] + g_bsum[idx >> 10];
        g_off[idx] = o;
        g_cursor[idx] = o;
    }
}

// ---------------------------------------------------------------------------
// Kernel 5: fill permuted edge list grouped by dst
// ---------------------------------------------------------------------------
__global__ __launch_bounds__(256) void fill_kernel(const int* __restrict__ ei) {
    int e = blockIdx.x * blockDim.x + threadIdx.x;
    if (e >= N_EDGES) return;
    int src = __ldg(&ei[e]);
    int dst = __ldg(&ei[N_EDGES + e]);
    int pos = atomicAdd(&g_cursor[dst], 1);
    g_edge[pos] = make_int2(e, src);
}

// ---------------------------------------------------------------------------
// Kernel 6: gather-side aggregation. One warp per node, float4 per lane.
// out[n] = bias + sum_{e: dst==n} relu(h[src_e] + edge_attr[e])
// ---------------------------------------------------------------------------
__global__ __launch_bounds__(256) void gather_kernel(const float* __restrict__ ea,
                                                     const float* __restrict__ bias,
                                                     float* __restrict__ out) {
    int n = blockIdx.x * (blockDim.x >> 5) + (threadIdx.x >> 5);
    if (n >= N_NODES) return;
    int lane = threadIdx.x & 31;

    int beg = __ldg(&g_off[n]);
    int end = __ldg(&g_off[n + 1]);

    float4 acc = make_float4(0.f, 0.f, 0.f, 0.f);
    for (int base = beg; base < end; base += 32) {
        int m = min(32, end - base);
        int2 es = (base + lane < end) ? __ldg(&g_edge[base + lane]) : make_int2(0, 0);
        #pragma unroll 4
        for (int j = 0; j < m; j++) {
            int e = __shfl_sync(0xFFFFFFFFu, es.x, j);
            int s = __shfl_sync(0xFFFFFFFFu, es.y, j);
            float4 a = __ldg(&((const float4*)(ea + (size_t)e * D))[lane]);
            float4 h = ((const float4*)(g_h + (size_t)s * D))[lane];
            acc.x += fmaxf(h.x + a.x, 0.f);
            acc.y += fmaxf(h.y + a.y, 0.f);
            acc.z += fmaxf(h.z + a.z, 0.f);
            acc.w += fmaxf(h.w + a.w, 0.f);
        }
    }
    float4 b = __ldg(&((const float4*)bias)[lane]);
    acc.x += b.x; acc.y += b.y; acc.z += b.z; acc.w += b.w;
    ((float4*)(out + (size_t)n * D))[lane] = acc;
}

// ---------------------------------------------------------------------------
extern "C" void kernel_launch(void* const* d_in, const int* in_sizes, int n_in,
                              void* d_out, int out_size) {
    const float* x    = (const float*)d_in[0];
    const int*   ei   = (const int*)d_in[1];   // int32 (JAX x64-disabled)
    const float* ea   = (const float*)d_in[2];
    const float* W    = (const float*)d_in[3];
    const float* bias = (const float*)d_in[4];
    float*       out  = (float*)d_out;

    zero_counts_kernel<<<(N_NODES + 255) / 256, 256>>>();
    hist_kernel<<<(N_EDGES / 4 + 255) / 256, 256>>>(ei);
    gemm_kernel<<<N_NODES / ROWS_PER_BLOCK, 128>>>(x, W);
    scan_local_kernel<<<SCAN_NB, 1024>>>();
    scan_bsum_kernel<<<1, 128>>>();
    scan_add_kernel<<<(N_NODES + 255) / 256, 256>>>();
    fill_kernel<<<(N_EDGES + 255) / 256, 256>>>(ei);
    gather_kernel<<<(N_NODES * 32 + 255) / 256, 256>>>(ea, bias, out);
}

// round 5
// speedup vs baseline: 1.3760x; 1.1145x over previous
#include <cuda_runtime.h>
#include <cstdint>

#define N_NODES 100000
#define N_EDGES 1600000
#define D 128
#define SCAN_NB 98  // ceil(100000 / 1024)

// Static scratch (no allocations allowed)
__device__ float g_h[(size_t)N_NODES * D];     // h = x @ W
__device__ int   g_count[N_NODES];             // per-dst degree histogram
__device__ int   g_off[N_NODES + 1];           // CSR row offsets
__device__ int   g_cursor[N_NODES];            // fill cursors
__device__ int   g_bsum[SCAN_NB];              // per-block scan sums
__device__ int2  g_edge[N_EDGES];              // (edge_id, src) grouped by dst

// ---------------------------------------------------------------------------
// Kernel 1: zero the histogram
// ---------------------------------------------------------------------------
__global__ void zero_counts_kernel() {
    int i = blockIdx.x * blockDim.x + threadIdx.x;
    if (i < N_NODES) g_count[i] = 0;
}

// ---------------------------------------------------------------------------
// Kernel 2: histogram of destination nodes (int4-vectorized reads)
// ---------------------------------------------------------------------------
__global__ __launch_bounds__(256) void hist_kernel(const int* __restrict__ ei) {
    int t = blockIdx.x * blockDim.x + threadIdx.x;  // one thread = 4 edges
    if (t * 4 >= N_EDGES) return;
    int4 d4 = __ldg(&((const int4*)(ei + N_EDGES))[t]);
    atomicAdd(&g_count[d4.x], 1);
    atomicAdd(&g_count[d4.y], 1);
    atomicAdd(&g_count[d4.z], 1);
    atomicAdd(&g_count[d4.w], 1);
}

// ---------------------------------------------------------------------------
// Kernel 3: h = x @ W  (4 warps/block, 4 rows/warp, float4 per lane)
// ---------------------------------------------------------------------------
#define ROWS_PER_WARP 4
#define ROWS_PER_BLOCK (4 * ROWS_PER_WARP)  // 16; 100000/16 = 6250 exact

__global__ __launch_bounds__(128) void gemm_kernel(const float* __restrict__ x,
                                                   const float* __restrict__ W) {
    __shared__ float xs[ROWS_PER_BLOCK][D];
    int tid  = threadIdx.x;
    int warp = tid >> 5;
    int lane = tid & 31;
    int row0 = blockIdx.x * ROWS_PER_BLOCK;

    const float4* xsrc = (const float4*)(x + (size_t)row0 * D);
    float4* xdst = (float4*)&xs[0][0];
    #pragma unroll
    for (int i = 0; i < ROWS_PER_BLOCK * D / 4 / 128; i++)
        xdst[tid + i * 128] = xsrc[tid + i * 128];
    __syncthreads();

    const float4* W4 = (const float4*)W;  // [D][32] float4
    for (int r = 0; r < ROWS_PER_WARP; r++) {
        int lr = warp * ROWS_PER_WARP + r;
        float4 acc = make_float4(0.f, 0.f, 0.f, 0.f);
        #pragma unroll
        for (int k = 0; k < D; k++) {
            float xv = xs[lr][k];
            float4 w = __ldg(&W4[k * 32 + lane]);
            acc.x += xv * w.x;
            acc.y += xv * w.y;
            acc.z += xv * w.z;
            acc.w += xv * w.w;
        }
        ((float4*)(g_h + (size_t)(row0 + lr) * D))[lane] = acc;
    }
}

// ---------------------------------------------------------------------------
// Kernel 4a: per-block local exclusive scan (98 blocks x 1024)
// ---------------------------------------------------------------------------
__global__ __launch_bounds__(1024) void scan_local_kernel() {
    __shared__ int wsum[32];
    int tid = threadIdx.x, lane = tid & 31, wid = tid >> 5;
    int idx = blockIdx.x * 1024 + tid;
    int v = (idx < N_NODES) ? g_count[idx] : 0;

    int inc = v;
    #pragma unroll
    for (int d = 1; d < 32; d <<= 1) {
        int t = __shfl_up_sync(0xFFFFFFFFu, inc, d);
        if (lane >= d) inc += t;
    }
    if (lane == 31) wsum[wid] = inc;
    __syncthreads();
    if (wid == 0) {
        int wv = wsum[lane];
        int winc = wv;
        #pragma unroll
        for (int d = 1; d < 32; d <<= 1) {
            int t = __shfl_up_sync(0xFFFFFFFFu, winc, d);
            if (lane >= d) winc += t;
        }
        wsum[lane] = winc - wv;
    }
    __syncthreads();
    int excl = wsum[wid] + inc - v;  // block-local exclusive
    if (idx < N_NODES) g_off[idx] = excl;
    if (tid == 1023) g_bsum[blockIdx.x] = excl + v;  // block total
}

// ---------------------------------------------------------------------------
// Kernel 4b: scan the 98 block sums (1 block, 128 threads)
// ---------------------------------------------------------------------------
__global__ __launch_bounds__(128) void scan_bsum_kernel() {
    __shared__ int wsum[4];
    int tid = threadIdx.x, lane = tid & 31, wid = tid >> 5;
    int v = (tid < SCAN_NB) ? g_bsum[tid] : 0;
    int inc = v;
    #pragma unroll
    for (int d = 1; d < 32; d <<= 1) {
        int t = __shfl_up_sync(0xFFFFFFFFu, inc, d);
        if (lane >= d) inc += t;
    }
    if (lane == 31) wsum[wid] = inc;
    __syncthreads();
    int woff = 0;
    for (int w = 0; w < wid; w++) woff += wsum[w];
    if (tid < SCAN_NB) g_bsum[tid] = woff + inc - v;  // exclusive
    if (tid == 127) g_off[N_NODES] = woff + inc;      // total == N_EDGES
}

// ---------------------------------------------------------------------------
// Kernel 4c: add block offsets -> final g_off, g_cursor
// ---------------------------------------------------------------------------
__global__ void scan_add_kernel() {
    int idx = blockIdx.x * blockDim.x + threadIdx.x;
    if (idx < N_NODES) {
        int o = g_off[idx] + g_bsum[idx >> 10];
        g_off[idx] = o;
        g_cursor[idx] = o;
    }
}

// ---------------------------------------------------------------------------
// Kernel 5: fill permuted edge list grouped by dst (4 edges per thread)
// ---------------------------------------------------------------------------
__global__ __launch_bounds__(256) void fill_kernel(const int* __restrict__ ei) {
    int t = blockIdx.x * blockDim.x + threadIdx.x;
    if (t * 4 >= N_EDGES) return;
    int4 s4 = __ldg(&((const int4*)ei)[t]);
    int4 d4 = __ldg(&((const int4*)(ei + N_EDGES))[t]);
    int e0 = t * 4;
    int p0 = atomicAdd(&g_cursor[d4.x], 1);
    int p1 = atomicAdd(&g_cursor[d4.y], 1);
    int p2 = atomicAdd(&g_cursor[d4.z], 1);
    int p3 = atomicAdd(&g_cursor[d4.w], 1);
    g_edge[p0] = make_int2(e0 + 0, s4.x);
    g_edge[p1] = make_int2(e0 + 1, s4.y);
    g_edge[p2] = make_int2(e0 + 2, s4.z);
    g_edge[p3] = make_int2(e0 + 3, s4.w);
}

// ---------------------------------------------------------------------------
// Kernel 6: gather-side aggregation. One warp per node, float4 per lane.
// out[n] = bias + sum_{e: dst==n} relu(h[src_e] + edge_attr[e])
// Streaming hints: ea / g_edge / out are single-use (evict-first), so g_h
// (51 MB) stays resident in the 126 MB L2.
// ---------------------------------------------------------------------------
__global__ __launch_bounds__(256) void gather_kernel(const float* __restrict__ ea,
                                                     const float* __restrict__ bias,
                                                     float* __restrict__ out) {
    int n = blockIdx.x * (blockDim.x >> 5) + (threadIdx.x >> 5);
    if (n >= N_NODES) return;
    int lane = threadIdx.x & 31;

    int beg = __ldg(&g_off[n]);
    int end = __ldg(&g_off[n + 1]);

    float4 acc = make_float4(0.f, 0.f, 0.f, 0.f);
    for (int base = beg; base < end; base += 32) {
        int m = min(32, end - base);
        int2 es = (base + lane < end) ? __ldcs(&g_edge[base + lane]) : make_int2(0, 0);
        #pragma unroll 4
        for (int j = 0; j < m; j++) {
            int e = __shfl_sync(0xFFFFFFFFu, es.x, j);
            int s = __shfl_sync(0xFFFFFFFFu, es.y, j);
            float4 a = __ldcs(&((const float4*)(ea + (size_t)e * D))[lane]);
            float4 h = __ldg(&((const float4*)(g_h + (size_t)s * D))[lane]);
            acc.x += fmaxf(h.x + a.x, 0.f);
            acc.y += fmaxf(h.y + a.y, 0.f);
            acc.z += fmaxf(h.z + a.z, 0.f);
            acc.w += fmaxf(h.w + a.w, 0.f);
        }
    }
    float4 b = __ldg(&((const float4*)bias)[lane]);
    acc.x += b.x; acc.y += b.y; acc.z += b.z; acc.w += b.w;
    __stcs(&((float4*)(out + (size_t)n * D))[lane], acc);
}

// ---------------------------------------------------------------------------
// Launch: fork the independent GEMM onto a side stream so it overlaps the
// CSR build chain; event-join before the gather. One-time stream/event
// creation (host-side resources only; no device allocations).
// ---------------------------------------------------------------------------
extern "C" void kernel_launch(void* const* d_in, const int* in_sizes, int n_in,
                              void* d_out, int out_size) {
    const float* x    = (const float*)d_in[0];
    const int*   ei   = (const int*)d_in[1];   // int32 (JAX x64-disabled)
    const float* ea   = (const float*)d_in[2];
    const float* W    = (const float*)d_in[3];
    const float* bias = (const float*)d_in[4];
    float*       out  = (float*)d_out;

    static cudaStream_t s2 = nullptr;
    static cudaEvent_t ev_fork = nullptr, ev_join = nullptr;
    if (s2 == nullptr) {
        cudaStreamCreateWithFlags(&s2, cudaStreamNonBlocking);
        cudaEventCreateWithFlags(&ev_fork, cudaEventDisableTiming);
        cudaEventCreateWithFlags(&ev_join, cudaEventDisableTiming);
    }

    // Fork: gemm on s2, CSR build on the main (captured) stream.
    cudaEventRecord(ev_fork, 0);
    cudaStreamWaitEvent(s2, ev_fork, 0);
    gemm_kernel<<<N_NODES / ROWS_PER_BLOCK, 128, 0, s2>>>(x, W);
    cudaEventRecord(ev_join, s2);

    zero_counts_kernel<<<(N_NODES + 255) / 256, 256>>>();
    hist_kernel<<<(N_EDGES / 4 + 255) / 256, 256>>>(ei);
    scan_local_kernel<<<SCAN_NB, 1024>>>();
    scan_bsum_kernel<<<1, 128>>>();
    scan_add_kernel<<<(N_NODES + 255) / 256, 256>>>();
    fill_kernel<<<(N_EDGES / 4 + 255) / 256, 256>>>(ei);

    // Join: gather needs both g_h (s2) and the CSR (main stream).
    cudaStreamWaitEvent(0, ev_join, 0);
    gather_kernel<<<(N_NODES * 32 + 255) / 256, 256>>>(ea, bias, out);
}